// round 1
// baseline (speedup 1.0000x reference)
#include <cuda_runtime.h>
#include <math.h>

#define N_NODES 50000
#define N_EDGES 500000
#define DIM 128
#define BN_EPS 1e-5f

// ---------------- scratch (device globals; no allocations allowed) ----------
__device__ float g_AX[N_NODES * DIM];
__device__ float g_BX[N_NODES * DIM];
__device__ float g_DX[N_NODES * DIM];
__device__ float g_EX[N_NODES * DIM];
__device__ float g_num[N_NODES * DIM];
__device__ float g_den[N_NODES * DIM];
__device__ float g_deg[N_NODES];
__device__ float g_hsum[DIM];
__device__ float g_hsq[DIM];
__device__ float g_esum[DIM];
__device__ float g_esq[DIM];

// ---------------- helpers ----------------------------------------------------
__device__ __forceinline__ void red_add_v4(float* addr, float a, float b, float c, float d) {
    asm volatile("red.global.add.v4.f32 [%0], {%1, %2, %3, %4};"
                 :: "l"(addr), "f"(a), "f"(b), "f"(c), "f"(d)
                 : "memory");
}

// ---------------- zero scratch ------------------------------------------------
__global__ void zero_scratch(float4* num4, float4* den4, float* deg,
                             float* hsum, float* hsq, float* esum, float* esq) {
    int i = blockIdx.x * blockDim.x + threadIdx.x;   // exactly N*D/4 threads
    float4 z = make_float4(0.f, 0.f, 0.f, 0.f);
    num4[i] = z;
    den4[i] = z;
    if (i < N_NODES) deg[i] = 0.f;
    if (i < DIM) { hsum[i] = 0.f; hsq[i] = 0.f; esum[i] = 0.f; esq[i] = 0.f; }
}

// ---------------- degree ------------------------------------------------------
__global__ void deg_kernel(const int* __restrict__ dst, float* __restrict__ deg) {
    int i = blockIdx.x * blockDim.x + threadIdx.x;
    if (i < N_EDGES) atomicAdd(&deg[dst[i]], 1.f);
}

// ---------------- node GEMM: out = A @ W + bias --------------------------------
// 64x128 tile, 256 threads, thread tile 4x8, k-step 16.
__global__ void gemm_bias(const float* __restrict__ A, const float* __restrict__ W,
                          const float* __restrict__ bias, float* __restrict__ out, int M) {
    __shared__ float As[16 * 64];
    __shared__ float Ws[16 * 128];
    int tid = threadIdx.x;
    int tx = tid & 15, ty = tid >> 4;
    int c0 = tx * 8, r0 = ty * 4;
    int rowBase = blockIdx.x * 64;

    float acc[4][8];
    #pragma unroll
    for (int i = 0; i < 4; i++)
        #pragma unroll
        for (int j = 0; j < 8; j++) acc[i][j] = 0.f;

    int lr = tid & 63;
    int lq = tid >> 6;
    int arow = min(rowBase + lr, M - 1);

    for (int k0 = 0; k0 < 128; k0 += 16) {
        float4 av = *(const float4*)&A[(long)arow * 128 + k0 + lq * 4];
        As[(lq * 4 + 0) * 64 + lr] = av.x;
        As[(lq * 4 + 1) * 64 + lr] = av.y;
        As[(lq * 4 + 2) * 64 + lr] = av.z;
        As[(lq * 4 + 3) * 64 + lr] = av.w;
        #pragma unroll
        for (int u = 0; u < 2; u++) {
            int i4 = tid * 2 + u;            // 0..511
            int kk = i4 >> 5;
            int cc = (i4 & 31) * 4;
            *(float4*)&Ws[kk * 128 + cc] = *(const float4*)&W[(k0 + kk) * 128 + cc];
        }
        __syncthreads();
        #pragma unroll
        for (int kk = 0; kk < 16; kk++) {
            float4 a4 = *(float4*)&As[kk * 64 + r0];
            float4 b0 = *(float4*)&Ws[kk * 128 + c0];
            float4 b1 = *(float4*)&Ws[kk * 128 + c0 + 4];
            float av4[4] = {a4.x, a4.y, a4.z, a4.w};
            float bv[8]  = {b0.x, b0.y, b0.z, b0.w, b1.x, b1.y, b1.z, b1.w};
            #pragma unroll
            for (int i = 0; i < 4; i++)
                #pragma unroll
                for (int j = 0; j < 8; j++) acc[i][j] += av4[i] * bv[j];
        }
        __syncthreads();
    }

    float bb[8];
    #pragma unroll
    for (int j = 0; j < 8; j++) bb[j] = __ldg(&bias[c0 + j]);

    #pragma unroll
    for (int i = 0; i < 4; i++) {
        int r = rowBase + r0 + i;
        if (r < M) {
            float4 o0 = make_float4(acc[i][0] + bb[0], acc[i][1] + bb[1],
                                    acc[i][2] + bb[2], acc[i][3] + bb[3]);
            float4 o1 = make_float4(acc[i][4] + bb[4], acc[i][5] + bb[5],
                                    acc[i][6] + bb[6], acc[i][7] + bb[7]);
            *(float4*)&out[(long)r * 128 + c0] = o0;
            *(float4*)&out[(long)r * 128 + c0 + 4] = o1;
        }
    }
}

// ---------------- fused edge kernel -------------------------------------------
// CE = E_X @ WC + bC (tiled GEMM), then per edge:
//   e_j = CE + DX[src] + EX[dst]; Epre = e_j * snorm_e -> d_out E region
//   sig = sigmoid(e_j); red num[dst] += sig*BX[src]; red den[dst] += sig
//   column sum/sumsq of Epre -> global stats (for BN over E)
__global__ void edge_kernel(const float* __restrict__ EXin, const float* __restrict__ W,
                            const float* __restrict__ bias,
                            const int* __restrict__ src, const int* __restrict__ dst,
                            const float* __restrict__ sne,
                            const float* __restrict__ BX, const float* __restrict__ DXn,
                            const float* __restrict__ EXn,
                            float* __restrict__ num, float* __restrict__ den,
                            float* __restrict__ outE,
                            float* __restrict__ esum, float* __restrict__ esq) {
    __shared__ float As[16 * 64];
    __shared__ float Ws[16 * 128];
    __shared__ int   s_src[64];
    __shared__ int   s_dst[64];
    __shared__ float s_sn[64];
    __shared__ float sm_sum[128];
    __shared__ float sm_sq[128];

    int tid = threadIdx.x;
    int tx = tid & 15, ty = tid >> 4;
    int c0 = tx * 8, r0 = ty * 4;
    int rowBase = blockIdx.x * 64;

    if (tid < 64) {
        int e = min(rowBase + tid, N_EDGES - 1);
        s_src[tid] = src[e];
        s_dst[tid] = dst[e];
        s_sn[tid]  = sne[e];
    }
    if (tid < 128) { sm_sum[tid] = 0.f; sm_sq[tid] = 0.f; }

    float acc[4][8];
    #pragma unroll
    for (int i = 0; i < 4; i++)
        #pragma unroll
        for (int j = 0; j < 8; j++) acc[i][j] = 0.f;

    int lr = tid & 63;
    int lq = tid >> 6;
    int arow = min(rowBase + lr, N_EDGES - 1);

    for (int k0 = 0; k0 < 128; k0 += 16) {
        float4 av = *(const float4*)&EXin[(long)arow * 128 + k0 + lq * 4];
        As[(lq * 4 + 0) * 64 + lr] = av.x;
        As[(lq * 4 + 1) * 64 + lr] = av.y;
        As[(lq * 4 + 2) * 64 + lr] = av.z;
        As[(lq * 4 + 3) * 64 + lr] = av.w;
        #pragma unroll
        for (int u = 0; u < 2; u++) {
            int i4 = tid * 2 + u;
            int kk = i4 >> 5;
            int cc = (i4 & 31) * 4;
            *(float4*)&Ws[kk * 128 + cc] = *(const float4*)&W[(k0 + kk) * 128 + cc];
        }
        __syncthreads();
        #pragma unroll
        for (int kk = 0; kk < 16; kk++) {
            float4 a4 = *(float4*)&As[kk * 64 + r0];
            float4 b0 = *(float4*)&Ws[kk * 128 + c0];
            float4 b1 = *(float4*)&Ws[kk * 128 + c0 + 4];
            float av4[4] = {a4.x, a4.y, a4.z, a4.w};
            float bv[8]  = {b0.x, b0.y, b0.z, b0.w, b1.x, b1.y, b1.z, b1.w};
            #pragma unroll
            for (int i = 0; i < 4; i++)
                #pragma unroll
                for (int j = 0; j < 8; j++) acc[i][j] += av4[i] * bv[j];
        }
        __syncthreads();
    }

    float bb[8];
    #pragma unroll
    for (int j = 0; j < 8; j++) bb[j] = __ldg(&bias[c0 + j]);

    float colsum[8], colsq[8];
    #pragma unroll
    for (int j = 0; j < 8; j++) { colsum[j] = 0.f; colsq[j] = 0.f; }

    #pragma unroll
    for (int i = 0; i < 4; i++) {
        int r = r0 + i;
        long e = (long)rowBase + r;
        if (e < N_EDGES) {
            int sv = s_src[r], dv = s_dst[r];
            float sn = s_sn[r];
            float4 dx0 = *(const float4*)&DXn[(long)sv * 128 + c0];
            float4 dx1 = *(const float4*)&DXn[(long)sv * 128 + c0 + 4];
            float4 ex0 = *(const float4*)&EXn[(long)dv * 128 + c0];
            float4 ex1 = *(const float4*)&EXn[(long)dv * 128 + c0 + 4];
            float4 bx0 = *(const float4*)&BX[(long)sv * 128 + c0];
            float4 bx1 = *(const float4*)&BX[(long)sv * 128 + c0 + 4];
            float dxv[8] = {dx0.x, dx0.y, dx0.z, dx0.w, dx1.x, dx1.y, dx1.z, dx1.w};
            float exv[8] = {ex0.x, ex0.y, ex0.z, ex0.w, ex1.x, ex1.y, ex1.z, ex1.w};
            float bxv[8] = {bx0.x, bx0.y, bx0.z, bx0.w, bx1.x, bx1.y, bx1.z, bx1.w};

            float ej[8], ep[8], sg[8], nb[8];
            #pragma unroll
            for (int j = 0; j < 8; j++) {
                ej[j] = acc[i][j] + bb[j] + dxv[j] + exv[j];
                ep[j] = ej[j] * sn;
                sg[j] = 1.f / (1.f + __expf(-ej[j]));
                nb[j] = sg[j] * bxv[j];
                colsum[j] += ep[j];
                colsq[j]  += ep[j] * ep[j];
            }
            *(float4*)&outE[e * 128 + c0]     = make_float4(ep[0], ep[1], ep[2], ep[3]);
            *(float4*)&outE[e * 128 + c0 + 4] = make_float4(ep[4], ep[5], ep[6], ep[7]);

            float* np = &num[(long)dv * 128 + c0];
            float* dp = &den[(long)dv * 128 + c0];
            red_add_v4(np,     nb[0], nb[1], nb[2], nb[3]);
            red_add_v4(np + 4, nb[4], nb[5], nb[6], nb[7]);
            red_add_v4(dp,     sg[0], sg[1], sg[2], sg[3]);
            red_add_v4(dp + 4, sg[4], sg[5], sg[6], sg[7]);
        }
    }

    // column stats: combine the two row-groups in each warp, then smem, then global
    #pragma unroll
    for (int j = 0; j < 8; j++) {
        colsum[j] += __shfl_xor_sync(0xffffffffu, colsum[j], 16);
        colsq[j]  += __shfl_xor_sync(0xffffffffu, colsq[j], 16);
    }
    if ((tid & 16) == 0) {
        #pragma unroll
        for (int j = 0; j < 8; j++) {
            atomicAdd(&sm_sum[c0 + j], colsum[j]);
            atomicAdd(&sm_sq[c0 + j],  colsq[j]);
        }
    }
    __syncthreads();
    if (tid < 128)      atomicAdd(&esum[tid], sm_sum[tid]);
    else                atomicAdd(&esq[tid - 128], sm_sq[tid - 128]);
}

// ---------------- node pre-BN: Hpre = gate-combine * snorm_n + stats ------------
__global__ void node_pre(const float* __restrict__ X, const float* __restrict__ AX,
                         const float* __restrict__ num, const float* __restrict__ den,
                         const float* __restrict__ deg, const float* __restrict__ snorm_n,
                         float* __restrict__ outH,
                         float* __restrict__ hsum, float* __restrict__ hsq) {
    __shared__ float sm1[128];
    __shared__ float sm2[128];
    int tid = threadIdx.x;
    if (tid < 128) { sm1[tid] = 0.f; sm2[tid] = 0.f; }
    __syncthreads();

    int c = tid & 127;
    int half = tid >> 7;
    int rBase = blockIdx.x * 64;
    int rEnd = min(rBase + 64, N_NODES);

    float s1 = 0.f, s2 = 0.f;
    for (int r = rBase + half; r < rEnd; r += 2) {
        float dg = deg[r];
        float sn = snorm_n[r];
        long idx = (long)r * 128 + c;
        float hv;
        if (dg > 0.f) {
            float dn = den[idx];
            float q = (dn > 0.f) ? (num[idx] / dn) : 0.f;
            hv = AX[idx] + q;
        } else {
            hv = X[idx];
        }
        hv *= sn;
        outH[idx] = hv;
        s1 += hv;
        s2 += hv * hv;
    }
    atomicAdd(&sm1[c], s1);
    atomicAdd(&sm2[c], s2);
    __syncthreads();
    if (tid < 128) atomicAdd(&hsum[tid], sm1[tid]);
    else           atomicAdd(&hsq[tid - 128], sm2[tid - 128]);
}

// ---------------- finalize: out = base + relu(BN(pre)) (in-place over pre) ------
__global__ void finalize_bn(const float* __restrict__ base, float* __restrict__ pre,
                            const float* __restrict__ sum, const float* __restrict__ sq,
                            const float* __restrict__ gamma, const float* __restrict__ beta,
                            long total4, float invn) {
    long i = (long)blockIdx.x * blockDim.x + threadIdx.x;
    if (i >= total4) return;
    int c4 = (int)(i & 31) * 4;
    float4 v  = ((const float4*)pre)[i];
    float4 xv = ((const float4*)base)[i];
    float vv[4] = {v.x, v.y, v.z, v.w};
    float xx[4] = {xv.x, xv.y, xv.z, xv.w};
    float oo[4];
    #pragma unroll
    for (int j = 0; j < 4; j++) {
        int c = c4 + j;
        float m   = __ldg(&sum[c]) * invn;
        float var = __ldg(&sq[c]) * invn - m * m;
        float rs  = rsqrtf(var + BN_EPS);
        float t = (vv[j] - m) * rs * __ldg(&gamma[c]) + __ldg(&beta[c]);
        oo[j] = xx[j] + fmaxf(t, 0.f);
    }
    ((float4*)pre)[i] = make_float4(oo[0], oo[1], oo[2], oo[3]);
}

// ---------------- launch --------------------------------------------------------
extern "C" void kernel_launch(void* const* d_in, const int* in_sizes, int n_in,
                              void* d_out, int out_size) {
    const float* X       = (const float*)d_in[0];
    const float* E_X     = (const float*)d_in[1];
    const int*   src     = (const int*)  d_in[2];
    const int*   dst     = (const int*)  d_in[3];
    const float* snorm_n = (const float*)d_in[4];
    const float* snorm_e = (const float*)d_in[5];
    const float* WA = (const float*)d_in[6];
    const float* bA = (const float*)d_in[7];
    const float* WB = (const float*)d_in[8];
    const float* bB = (const float*)d_in[9];
    const float* WC = (const float*)d_in[10];
    const float* bC = (const float*)d_in[11];
    const float* WD = (const float*)d_in[12];
    const float* bD = (const float*)d_in[13];
    const float* WE = (const float*)d_in[14];
    const float* bE = (const float*)d_in[15];
    const float* gamma_h = (const float*)d_in[16];
    const float* beta_h  = (const float*)d_in[17];
    const float* gamma_e = (const float*)d_in[18];
    const float* beta_e  = (const float*)d_in[19];

    float* out  = (float*)d_out;
    float* outH = out;
    float* outE = out + (long)N_NODES * DIM;

    float *pAX, *pBX, *pDX, *pEX, *pnum, *pden, *pdeg;
    float *phsum, *phsq, *pesum, *pesq;
    cudaGetSymbolAddress((void**)&pAX, g_AX);
    cudaGetSymbolAddress((void**)&pBX, g_BX);
    cudaGetSymbolAddress((void**)&pDX, g_DX);
    cudaGetSymbolAddress((void**)&pEX, g_EX);
    cudaGetSymbolAddress((void**)&pnum, g_num);
    cudaGetSymbolAddress((void**)&pden, g_den);
    cudaGetSymbolAddress((void**)&pdeg, g_deg);
    cudaGetSymbolAddress((void**)&phsum, g_hsum);
    cudaGetSymbolAddress((void**)&phsq, g_hsq);
    cudaGetSymbolAddress((void**)&pesum, g_esum);
    cudaGetSymbolAddress((void**)&pesq, g_esq);

    // 1. zero scratch (N*D/4 = 1,600,000 threads exactly)
    zero_scratch<<<6250, 256>>>((float4*)pnum, (float4*)pden, pdeg,
                                phsum, phsq, pesum, pesq);

    // 2. node GEMMs
    int nodeBlocks = (N_NODES + 63) / 64;   // 782
    gemm_bias<<<nodeBlocks, 256>>>(X, WA, bA, pAX, N_NODES);
    gemm_bias<<<nodeBlocks, 256>>>(X, WB, bB, pBX, N_NODES);
    gemm_bias<<<nodeBlocks, 256>>>(X, WD, bD, pDX, N_NODES);
    gemm_bias<<<nodeBlocks, 256>>>(X, WE, bE, pEX, N_NODES);

    // 3. degrees
    deg_kernel<<<(N_EDGES + 255) / 256, 256>>>(dst, pdeg);

    // 4. fused edge kernel (CE GEMM + message + gated scatter + E stats)
    int edgeBlocks = (N_EDGES + 63) / 64;   // 7813
    edge_kernel<<<edgeBlocks, 256>>>(E_X, WC, bC, src, dst, snorm_e,
                                     pBX, pDX, pEX, pnum, pden, outE, pesum, pesq);

    // 5. node combine + H stats
    node_pre<<<nodeBlocks, 256>>>(X, pAX, pnum, pden, pdeg, snorm_n,
                                  outH, phsum, phsq);

    // 6. finalize H: out = X + relu(BN(Hpre))
    long h4 = (long)N_NODES * DIM / 4;       // 1.6M
    finalize_bn<<<(int)((h4 + 255) / 256), 256>>>(X, outH, phsum, phsq,
                                                  gamma_h, beta_h, h4, 1.f / N_NODES);

    // 7. finalize E: out = E_X + relu(BN(Epre))
    long e4 = (long)N_EDGES * DIM / 4;       // 16M
    finalize_bn<<<(int)((e4 + 255) / 256), 256>>>(E_X, outE, pesum, pesq,
                                                  gamma_e, beta_e, e4, 1.f / N_EDGES);
}

// round 2
// speedup vs baseline: 1.4289x; 1.4289x over previous
#include <cuda_runtime.h>
#include <math.h>

#define N_NODES 50000
#define N_EDGES 500000
#define DIM 128
#define BN_EPS 1e-5f

// ---------------- scratch (device globals; no allocations allowed) ----------
__device__ float g_AX[N_NODES * DIM];
__device__ float g_BX[N_NODES * DIM];
__device__ float g_DX[N_NODES * DIM];
__device__ float g_EX[N_NODES * DIM];
__device__ float g_num[N_NODES * DIM];
__device__ float g_den[N_NODES * DIM];
__device__ float g_deg[N_NODES];
__device__ float g_hsum[DIM];
__device__ float g_hsq[DIM];
__device__ float g_esum[DIM];
__device__ float g_esq[DIM];

// ---------------- helpers ----------------------------------------------------
__device__ __forceinline__ void red_add_v4(float* addr, float a, float b, float c, float d) {
    asm volatile("red.global.add.v4.f32 [%0], {%1, %2, %3, %4};"
                 :: "l"(addr), "f"(a), "f"(b), "f"(c), "f"(d)
                 : "memory");
}

// ---------------- zero scratch ------------------------------------------------
__global__ void zero_scratch(float4* num4, float4* den4, float* deg,
                             float* hsum, float* hsq, float* esum, float* esq) {
    int i = blockIdx.x * blockDim.x + threadIdx.x;   // exactly N*D/4 threads
    float4 z = make_float4(0.f, 0.f, 0.f, 0.f);
    num4[i] = z;
    den4[i] = z;
    if (i < N_NODES) deg[i] = 0.f;
    if (i < DIM) { hsum[i] = 0.f; hsq[i] = 0.f; esum[i] = 0.f; esq[i] = 0.f; }
}

// ---------------- degree ------------------------------------------------------
__global__ void deg_kernel(const int* __restrict__ dst, float* __restrict__ deg) {
    int i = blockIdx.x * blockDim.x + threadIdx.x;
    if (i < N_EDGES) atomicAdd(&deg[dst[i]], 1.f);
}

// ================================================================================
// Shared GEMM core: 128x128 block tile, 256 threads, 8x8 microtile, k-step 32.
// As stored [k][row] (transposed on load), Ws stored [k][col].
// acc[8][8] accumulates rows r0..r0+7 x cols c0..c0+7.
// ================================================================================
__device__ __forceinline__ void gemm_tile_128(
    const float* __restrict__ A, const float* __restrict__ W,
    int rowBase, int M, int tid, float* As, float* Ws, float acc[8][8])
{
    int tx = tid & 15, ty = tid >> 4;
    int c0 = tx * 8, r0 = ty * 8;

    #pragma unroll
    for (int i = 0; i < 8; i++)
        #pragma unroll
        for (int j = 0; j < 8; j++) acc[i][j] = 0.f;

    #pragma unroll
    for (int k0 = 0; k0 < 128; k0 += 32) {
        // load A tile 128 rows x 32 k (transposed into As[k][row])
        #pragma unroll
        for (int u = 0; u < 4; u++) {
            int idx = tid + u * 256;            // 0..1023
            int r  = idx & 127;
            int kc = (idx >> 7) * 4;            // 0,4,...,28
            int grow = min(rowBase + r, M - 1);
            float4 av = *(const float4*)&A[(long)grow * 128 + k0 + kc];
            As[(kc + 0) * 128 + r] = av.x;
            As[(kc + 1) * 128 + r] = av.y;
            As[(kc + 2) * 128 + r] = av.z;
            As[(kc + 3) * 128 + r] = av.w;
        }
        // load W tile 32 k x 128 cols (direct copy)
        #pragma unroll
        for (int u = 0; u < 4; u++) {
            int idx = tid + u * 256;
            int kk = idx >> 5;                  // 0..31
            int cc = (idx & 31) * 4;
            *(float4*)&Ws[kk * 128 + cc] = *(const float4*)&W[(k0 + kk) * 128 + cc];
        }
        __syncthreads();
        #pragma unroll 8
        for (int kk = 0; kk < 32; kk++) {
            float4 a0 = *(float4*)&As[kk * 128 + r0];
            float4 a1 = *(float4*)&As[kk * 128 + r0 + 4];
            float4 w0 = *(float4*)&Ws[kk * 128 + c0];
            float4 w1 = *(float4*)&Ws[kk * 128 + c0 + 4];
            float av[8] = {a0.x, a0.y, a0.z, a0.w, a1.x, a1.y, a1.z, a1.w};
            float wv[8] = {w0.x, w0.y, w0.z, w0.w, w1.x, w1.y, w1.z, w1.w};
            #pragma unroll
            for (int i = 0; i < 8; i++)
                #pragma unroll
                for (int j = 0; j < 8; j++) acc[i][j] += av[i] * wv[j];
        }
        __syncthreads();
    }
}

// ---------------- fused node GEMMs: grid.y in {0..3} selects (W, bias, out) -----
__global__ __launch_bounds__(256, 2)
void gemm_bias(const float* __restrict__ A,
               const float* __restrict__ W0, const float* __restrict__ b0, float* __restrict__ o0,
               const float* __restrict__ W1, const float* __restrict__ b1, float* __restrict__ o1,
               const float* __restrict__ W2, const float* __restrict__ b2, float* __restrict__ o2,
               const float* __restrict__ W3, const float* __restrict__ b3, float* __restrict__ o3,
               int M) {
    __shared__ float As[32 * 128];
    __shared__ float Ws[32 * 128];
    const float *W, *bias;
    float* out;
    switch (blockIdx.y) {
        case 0:  W = W0; bias = b0; out = o0; break;
        case 1:  W = W1; bias = b1; out = o1; break;
        case 2:  W = W2; bias = b2; out = o2; break;
        default: W = W3; bias = b3; out = o3; break;
    }
    int tid = threadIdx.x;
    int tx = tid & 15, ty = tid >> 4;
    int c0 = tx * 8, r0 = ty * 8;
    int rowBase = blockIdx.x * 128;

    float acc[8][8];
    gemm_tile_128(A, W, rowBase, M, tid, As, Ws, acc);

    float bb[8];
    #pragma unroll
    for (int j = 0; j < 8; j++) bb[j] = __ldg(&bias[c0 + j]);

    #pragma unroll
    for (int i = 0; i < 8; i++) {
        int r = rowBase + r0 + i;
        if (r < M) {
            float4 q0 = make_float4(acc[i][0] + bb[0], acc[i][1] + bb[1],
                                    acc[i][2] + bb[2], acc[i][3] + bb[3]);
            float4 q1 = make_float4(acc[i][4] + bb[4], acc[i][5] + bb[5],
                                    acc[i][6] + bb[6], acc[i][7] + bb[7]);
            *(float4*)&out[(long)r * 128 + c0]     = q0;
            *(float4*)&out[(long)r * 128 + c0 + 4] = q1;
        }
    }
}

// ---------------- fused edge kernel -------------------------------------------
// CE = E_X @ WC + bC (128x128-tile GEMM), then per edge:
//   e_j = CE + DX[src] + EX[dst]; Epre = e_j * snorm_e -> d_out E region
//   sig = sigmoid(e_j); red num[dst] += sig*BX[src]; red den[dst] += sig
//   column sum/sumsq of Epre -> global stats (for BN over E)
__global__ __launch_bounds__(256, 2)
void edge_kernel(const float* __restrict__ EXin, const float* __restrict__ W,
                 const float* __restrict__ bias,
                 const int* __restrict__ src, const int* __restrict__ dst,
                 const float* __restrict__ sne,
                 const float* __restrict__ BX, const float* __restrict__ DXn,
                 const float* __restrict__ EXn,
                 float* __restrict__ num, float* __restrict__ den,
                 float* __restrict__ outE,
                 float* __restrict__ esum, float* __restrict__ esq) {
    __shared__ float As[32 * 128];
    __shared__ float Ws[32 * 128];
    __shared__ int   s_src[128];
    __shared__ int   s_dst[128];
    __shared__ float s_sn[128];
    __shared__ float sm_sum[128];
    __shared__ float sm_sq[128];

    int tid = threadIdx.x;
    int tx = tid & 15, ty = tid >> 4;
    int c0 = tx * 8, r0 = ty * 8;
    int rowBase = blockIdx.x * 128;

    if (tid < 128) {
        int e = min(rowBase + tid, N_EDGES - 1);
        s_src[tid] = src[e];
        s_dst[tid] = dst[e];
        s_sn[tid]  = sne[e];
        sm_sum[tid] = 0.f;
        sm_sq[tid]  = 0.f;
    }

    float acc[8][8];
    gemm_tile_128(EXin, W, rowBase, N_EDGES, tid, As, Ws, acc);

    float bb[8];
    #pragma unroll
    for (int j = 0; j < 8; j++) bb[j] = __ldg(&bias[c0 + j]);

    float colsum[8], colsq[8];
    #pragma unroll
    for (int j = 0; j < 8; j++) { colsum[j] = 0.f; colsq[j] = 0.f; }

    #pragma unroll
    for (int i = 0; i < 8; i++) {
        int r = r0 + i;
        long e = (long)rowBase + r;
        if (e < N_EDGES) {
            int sv = s_src[r], dv = s_dst[r];
            float sn = s_sn[r];
            float4 dx0 = *(const float4*)&DXn[(long)sv * 128 + c0];
            float4 dx1 = *(const float4*)&DXn[(long)sv * 128 + c0 + 4];
            float4 ex0 = *(const float4*)&EXn[(long)dv * 128 + c0];
            float4 ex1 = *(const float4*)&EXn[(long)dv * 128 + c0 + 4];
            float4 bx0 = *(const float4*)&BX[(long)sv * 128 + c0];
            float4 bx1 = *(const float4*)&BX[(long)sv * 128 + c0 + 4];
            float dxv[8] = {dx0.x, dx0.y, dx0.z, dx0.w, dx1.x, dx1.y, dx1.z, dx1.w};
            float exv[8] = {ex0.x, ex0.y, ex0.z, ex0.w, ex1.x, ex1.y, ex1.z, ex1.w};
            float bxv[8] = {bx0.x, bx0.y, bx0.z, bx0.w, bx1.x, bx1.y, bx1.z, bx1.w};

            float ej[8], ep[8], sg[8], nb[8];
            #pragma unroll
            for (int j = 0; j < 8; j++) {
                ej[j] = acc[i][j] + bb[j] + dxv[j] + exv[j];
                ep[j] = ej[j] * sn;
                sg[j] = 1.f / (1.f + __expf(-ej[j]));
                nb[j] = sg[j] * bxv[j];
                colsum[j] += ep[j];
                colsq[j]  += ep[j] * ep[j];
            }
            *(float4*)&outE[e * 128 + c0]     = make_float4(ep[0], ep[1], ep[2], ep[3]);
            *(float4*)&outE[e * 128 + c0 + 4] = make_float4(ep[4], ep[5], ep[6], ep[7]);

            float* np = &num[(long)dv * 128 + c0];
            float* dp = &den[(long)dv * 128 + c0];
            red_add_v4(np,     nb[0], nb[1], nb[2], nb[3]);
            red_add_v4(np + 4, nb[4], nb[5], nb[6], nb[7]);
            red_add_v4(dp,     sg[0], sg[1], sg[2], sg[3]);
            red_add_v4(dp + 4, sg[4], sg[5], sg[6], sg[7]);
        }
    }

    // column stats: combine ty-pairs within warp (tid^16 flips ty bit0), then smem, then global
    #pragma unroll
    for (int j = 0; j < 8; j++) {
        colsum[j] += __shfl_xor_sync(0xffffffffu, colsum[j], 16);
        colsq[j]  += __shfl_xor_sync(0xffffffffu, colsq[j], 16);
    }
    if ((tid & 16) == 0) {
        #pragma unroll
        for (int j = 0; j < 8; j++) {
            atomicAdd(&sm_sum[c0 + j], colsum[j]);
            atomicAdd(&sm_sq[c0 + j],  colsq[j]);
        }
    }
    __syncthreads();
    if (tid < 128)      atomicAdd(&esum[tid], sm_sum[tid]);
    else                atomicAdd(&esq[tid - 128], sm_sq[tid - 128]);
}

// ---------------- node pre-BN: Hpre = gate-combine * snorm_n + stats ------------
__global__ void node_pre(const float* __restrict__ X, const float* __restrict__ AX,
                         const float* __restrict__ num, const float* __restrict__ den,
                         const float* __restrict__ deg, const float* __restrict__ snorm_n,
                         float* __restrict__ outH,
                         float* __restrict__ hsum, float* __restrict__ hsq) {
    __shared__ float sm1[128];
    __shared__ float sm2[128];
    int tid = threadIdx.x;
    if (tid < 128) { sm1[tid] = 0.f; sm2[tid] = 0.f; }
    __syncthreads();

    int c = tid & 127;
    int half = tid >> 7;
    int rBase = blockIdx.x * 64;
    int rEnd = min(rBase + 64, N_NODES);

    float s1 = 0.f, s2 = 0.f;
    for (int r = rBase + half; r < rEnd; r += 2) {
        float dg = deg[r];
        float sn = snorm_n[r];
        long idx = (long)r * 128 + c;
        float hv;
        if (dg > 0.f) {
            float dn = den[idx];
            float q = (dn > 0.f) ? (num[idx] / dn) : 0.f;
            hv = AX[idx] + q;
        } else {
            hv = X[idx];
        }
        hv *= sn;
        outH[idx] = hv;
        s1 += hv;
        s2 += hv * hv;
    }
    atomicAdd(&sm1[c], s1);
    atomicAdd(&sm2[c], s2);
    __syncthreads();
    if (tid < 128) atomicAdd(&hsum[tid], sm1[tid]);
    else           atomicAdd(&hsq[tid - 128], sm2[tid - 128]);
}

// ---------------- finalize: out = base + relu(BN(pre)) (in-place over pre) ------
__global__ void finalize_bn(const float* __restrict__ base, float* __restrict__ pre,
                            const float* __restrict__ sum, const float* __restrict__ sq,
                            const float* __restrict__ gamma, const float* __restrict__ beta,
                            long total4, float invn) {
    long i = (long)blockIdx.x * blockDim.x + threadIdx.x;
    if (i >= total4) return;
    int c4 = (int)(i & 31) * 4;
    float4 v  = ((const float4*)pre)[i];
    float4 xv = ((const float4*)base)[i];
    float vv[4] = {v.x, v.y, v.z, v.w};
    float xx[4] = {xv.x, xv.y, xv.z, xv.w};
    float oo[4];
    #pragma unroll
    for (int j = 0; j < 4; j++) {
        int c = c4 + j;
        float m   = __ldg(&sum[c]) * invn;
        float var = __ldg(&sq[c]) * invn - m * m;
        float rs  = rsqrtf(var + BN_EPS);
        float t = (vv[j] - m) * rs * __ldg(&gamma[c]) + __ldg(&beta[c]);
        oo[j] = xx[j] + fmaxf(t, 0.f);
    }
    ((float4*)pre)[i] = make_float4(oo[0], oo[1], oo[2], oo[3]);
}

// ---------------- launch --------------------------------------------------------
extern "C" void kernel_launch(void* const* d_in, const int* in_sizes, int n_in,
                              void* d_out, int out_size) {
    const float* X       = (const float*)d_in[0];
    const float* E_X     = (const float*)d_in[1];
    const int*   src     = (const int*)  d_in[2];
    const int*   dst     = (const int*)  d_in[3];
    const float* snorm_n = (const float*)d_in[4];
    const float* snorm_e = (const float*)d_in[5];
    const float* WA = (const float*)d_in[6];
    const float* bA = (const float*)d_in[7];
    const float* WB = (const float*)d_in[8];
    const float* bB = (const float*)d_in[9];
    const float* WC = (const float*)d_in[10];
    const float* bC = (const float*)d_in[11];
    const float* WD = (const float*)d_in[12];
    const float* bD = (const float*)d_in[13];
    const float* WE = (const float*)d_in[14];
    const float* bE = (const float*)d_in[15];
    const float* gamma_h = (const float*)d_in[16];
    const float* beta_h  = (const float*)d_in[17];
    const float* gamma_e = (const float*)d_in[18];
    const float* beta_e  = (const float*)d_in[19];

    float* out  = (float*)d_out;
    float* outH = out;
    float* outE = out + (long)N_NODES * DIM;

    float *pAX, *pBX, *pDX, *pEX, *pnum, *pden, *pdeg;
    float *phsum, *phsq, *pesum, *pesq;
    cudaGetSymbolAddress((void**)&pAX, g_AX);
    cudaGetSymbolAddress((void**)&pBX, g_BX);
    cudaGetSymbolAddress((void**)&pDX, g_DX);
    cudaGetSymbolAddress((void**)&pEX, g_EX);
    cudaGetSymbolAddress((void**)&pnum, g_num);
    cudaGetSymbolAddress((void**)&pden, g_den);
    cudaGetSymbolAddress((void**)&pdeg, g_deg);
    cudaGetSymbolAddress((void**)&phsum, g_hsum);
    cudaGetSymbolAddress((void**)&phsq, g_hsq);
    cudaGetSymbolAddress((void**)&pesum, g_esum);
    cudaGetSymbolAddress((void**)&pesq, g_esq);

    // 1. zero scratch (N*D/4 = 1,600,000 threads exactly)
    zero_scratch<<<6250, 256>>>((float4*)pnum, (float4*)pden, pdeg,
                                phsum, phsq, pesum, pesq);

    // 2. node GEMMs (fused: grid.y selects A/B/D/E weights)
    dim3 ngrid((N_NODES + 127) / 128, 4);   // 391 x 4
    gemm_bias<<<ngrid, 256>>>(X,
                              WA, bA, pAX,
                              WB, bB, pBX,
                              WD, bD, pDX,
                              WE, bE, pEX,
                              N_NODES);

    // 3. degrees
    deg_kernel<<<(N_EDGES + 255) / 256, 256>>>(dst, pdeg);

    // 4. fused edge kernel (CE GEMM + message + gated scatter + E stats)
    int edgeBlocks = (N_EDGES + 127) / 128;   // 3907
    edge_kernel<<<edgeBlocks, 256>>>(E_X, WC, bC, src, dst, snorm_e,
                                     pBX, pDX, pEX, pnum, pden, outE, pesum, pesq);

    // 5. node combine + H stats
    node_pre<<<(N_NODES + 63) / 64, 256>>>(X, pAX, pnum, pden, pdeg, snorm_n,
                                           outH, phsum, phsq);

    // 6. finalize H: out = X + relu(BN(Hpre))
    long h4 = (long)N_NODES * DIM / 4;       // 1.6M
    finalize_bn<<<(int)((h4 + 255) / 256), 256>>>(X, outH, phsum, phsq,
                                                  gamma_h, beta_h, h4, 1.f / N_NODES);

    // 7. finalize E: out = E_X + relu(BN(Epre))
    long e4 = (long)N_EDGES * DIM / 4;       // 16M
    finalize_bn<<<(int)((e4 + 255) / 256), 256>>>(E_X, outE, pesum, pesq,
                                                  gamma_e, beta_e, e4, 1.f / N_EDGES);
}